// round 8
// baseline (speedup 1.0000x reference)
#include <cuda_runtime.h>
#include <cuda_bf16.h>
#include <cstdint>

// Clipped Poisson-binomial severity kernel, round 7.
// Persistent blocks (4/SM, the proven concurrency level) with a 3-slot ring of
// 16KB cp.async.bulk chunks. The TMA queue never drains across tiles: as soon
// as a block-wide sync frees a slot, thread 0 reissues it for chunk j+3.
// Consumption (scalar 6-fma recurrence), rotation-ordered conflict-free LDS,
// and staged evict-first float4 output stores are unchanged from round 6.

#define NT 128                       // threads per block
#define ROWS 128                     // rows per tile (1 per thread)
#define CHUNK_FLOATS (ROWS * 32)     // 4096 floats = 16 KB per (tile,input) chunk
#define NSLOTS 3
#define SMEM_BYTES ((NSLOTS * CHUNK_FLOATS + ROWS * 5) * 4)   // 51,712 B

__device__ __forceinline__ void mbar_wait(unsigned mb, unsigned parity) {
    unsigned done;
    asm volatile(
        "{\n\t.reg .pred p;\n\t"
        "mbarrier.try_wait.parity.acquire.cta.shared::cta.b64 p, [%1], %2, 0x989680;\n\t"
        "selp.b32 %0, 1, 0, p;\n\t}"
        : "=r"(done) : "r"(mb), "r"(parity) : "memory");
    while (!done) {
        asm volatile(
            "{\n\t.reg .pred p;\n\t"
            "mbarrier.try_wait.parity.acquire.cta.shared::cta.b64 p, [%1], %2, 0x989680;\n\t"
            "selp.b32 %0, 1, 0, p;\n\t}"
            : "=r"(done) : "r"(mb), "r"(parity) : "memory");
    }
}

__global__ void __launch_bounds__(NT, 4)
hemorrhage_sev_kernel(const float* __restrict__ x1,
                      const float* __restrict__ x2,
                      const float* __restrict__ x3,
                      float* __restrict__ out,
                      int nrows, int ntiles)
{
    extern __shared__ float s[];
    float* ring = s;                                // NSLOTS * 16 KB
    float* so   = s + NSLOTS * CHUNK_FLOATS;        // 640 floats output staging
    __shared__ __align__(8) unsigned long long mbar[NSLOTS];

    const int t = threadIdx.x;
    const float* srcs[3] = { x1, x2, x3 };

    if (t == 0) {
        #pragma unroll
        for (int sl = 0; sl < NSLOTS; ++sl) {
            unsigned mb = (unsigned)__cvta_generic_to_shared(&mbar[sl]);
            asm volatile("mbarrier.init.shared.b64 [%0], 1;" :: "r"(mb));
        }
    }
    __syncthreads();

    const int firstTile = blockIdx.x;
    const int stride    = gridDim.x;
    const int nMine     = (ntiles - firstTile + stride - 1) / stride;  // >= 1
    const int T         = 3 * nMine;                // total chunks for this block

    // issue chunk j (j/3-th of my tiles, input j%3) into ring slot j%3
    auto issue = [&](int j) {
        const int ti = j / 3, in = j - 3 * ti;
        const long long tile    = (long long)firstTile + (long long)ti * stride;
        const long long rowBase = tile * ROWS;
        const int rowsHere = (int)min((long long)ROWS, (long long)nrows - rowBase);
        const unsigned bytes = (unsigned)(rowsHere * 128);
        const int slot = j % NSLOTS;
        unsigned mb  = (unsigned)__cvta_generic_to_shared(&mbar[slot]);
        unsigned dst = (unsigned)__cvta_generic_to_shared(ring + slot * CHUNK_FLOATS);
        const float* src = srcs[in] + rowBase * 32;
        asm volatile("mbarrier.arrive.expect_tx.shared.b64 _, [%0], %1;"
                     :: "r"(mb), "r"(bytes));
        asm volatile(
            "cp.async.bulk.shared::cta.global.mbarrier::complete_tx::bytes "
            "[%0], [%1], %2, [%3];"
            :: "r"(dst), "l"(src), "r"(bytes), "r"(mb) : "memory");
    };

    if (t == 0) {
        const int pro = T < NSLOTS ? T : NSLOTS;
        for (int j = 0; j < pro; ++j) issue(j);
    }
    // no extra sync needed: mbar init already sync'd; consumers block on phases

    float c0 = 1.f, c1 = 0.f, c2 = 0.f, c3 = 0.f, c4 = 0.f, c5 = 0.f;
    const int rot = t & 7;

    for (int j = 0; j < T; ++j) {
        const int slot = j % NSLOTS;
        const unsigned parity = (unsigned)((j / NSLOTS) & 1);
        unsigned mb = (unsigned)__cvta_generic_to_shared(&mbar[slot]);
        mbar_wait(mb, parity);

        if (j % 3 == 0) { c0 = 1.f; c1 = c2 = c3 = c4 = c5 = 0.f; }

        // rotation-ordered conflict-free LDS.128 from this slot's row
        const float4* rowp = (const float4*)(ring + slot * CHUNK_FLOATS + t * 32);
        #pragma unroll
        for (int i = 0; i < 8; ++i) {
            float4 v = rowp[(rot + i) & 7];
            float pv[4] = { v.x, v.y, v.z, v.w };
            #pragma unroll
            for (int u = 0; u < 4; ++u) {
                float p = pv[u];
                c5 = fmaf(c4, p, c5);            // absorbing top bucket (old c4)
                c4 = fmaf(c3 - c4, p, c4);
                c3 = fmaf(c2 - c3, p, c3);
                c2 = fmaf(c1 - c2, p, c2);
                c1 = fmaf(c0 - c1, p, c1);
                c0 = fmaf(-c0, p, c0);           // c0 *= (1-p)
            }
        }

        const bool lastOfTile = (j % 3 == 2);
        if (lastOfTile) {                        // stage outputs (stride-5: conflict-free)
            so[t * 5 + 0] = c0;
            so[t * 5 + 1] = c1 + c2;
            so[t * 5 + 2] = c3 + c4;
            so[t * 5 + 3] = c5;
            so[t * 5 + 4] = 0.f;
        }

        __syncthreads();                         // slot j%3 now free; so visible

        if (t == 0 && j + NSLOTS < T) issue(j + NSLOTS);   // refill immediately

        if (lastOfTile) {
            const int ti = j / 3;
            const long long tile    = (long long)firstTile + (long long)ti * stride;
            const long long rowBase = tile * ROWS;
            const int rowsHere = (int)min((long long)ROWS, (long long)nrows - rowBase);
            float* og = out + rowBase * 5;
            if (rowsHere == ROWS) {
                float4* og4 = (float4*)og;       // 2560 B/tile -> 16B-aligned base
                const float4* so4 = (const float4*)so;
                #pragma unroll
                for (int k = 0; k < 2; ++k) {
                    int idx = k * NT + t;
                    if (idx < (ROWS * 5) / 4) __stcs(og4 + idx, so4[idx]);
                }
            } else {
                const int nOut = rowsHere * 5;
                #pragma unroll
                for (int k = 0; k < 5; ++k) {
                    int idx = k * NT + t;
                    if (idx < nOut) og[idx] = so[idx];
                }
            }
        }
    }
}

extern "C" void kernel_launch(void* const* d_in, const int* in_sizes, int n_in,
                              void* d_out, int out_size)
{
    const float* x1 = (const float*)d_in[0];
    const float* x2 = (const float*)d_in[1];
    const float* x3 = (const float*)d_in[2];
    float* out = (float*)d_out;

    const int nrows  = in_sizes[0] / 32;
    const int ntiles = (nrows + ROWS - 1) / ROWS;

    int dev = 0, nsm = 148;
    cudaGetDevice(&dev);
    cudaDeviceGetAttribute(&nsm, cudaDevAttrMultiProcessorCount, dev);

    static bool attrSet = false;
    if (!attrSet) {
        cudaFuncSetAttribute(hemorrhage_sev_kernel,
                             cudaFuncAttributeMaxDynamicSharedMemorySize, SMEM_BYTES);
        attrSet = true;
    }

    int grid = 4 * nsm;
    if (grid > ntiles) grid = ntiles;

    hemorrhage_sev_kernel<<<grid, NT, SMEM_BYTES>>>(x1, x2, x3, out, nrows, ntiles);
}

// round 9
// speedup vs baseline: 1.0846x; 1.0846x over previous
#include <cuda_runtime.h>
#include <cuda_bf16.h>
#include <cstdint>

// Clipped Poisson-binomial severity kernel, round 8.
// Identical structure to round 6 (best: one-shot independent blocks, 3 bulk
// copies per block with per-input mbarriers and progressive waits, scalar
// recurrence, rotation-ordered conflict-free LDS, staged .cs float4 stores),
// but half-size tiles: ROWS=64 / NT=64 / 24.6KB smem -> ~8 blocks/SM, doubling
// the number of independent in-flight bulk streams per SM to smooth DRAM demand.

#define NT 64                // threads per block
#define ROWS 64              // rows per block (1 per thread)
#define IN_FLOATS (ROWS * 32)        // 2048 floats = 8 KB per input tile

__global__ __launch_bounds__(NT)
void hemorrhage_sev_kernel(const float* __restrict__ x1,
                           const float* __restrict__ x2,
                           const float* __restrict__ x3,
                           float* __restrict__ out,
                           int nrows)
{
    __shared__ float s[3 * IN_FLOATS];              // 24,576 B, raw 128B rows
    __shared__ __align__(8) unsigned long long mbar[3];

    const int t = threadIdx.x;
    const long long rowBase = (long long)blockIdx.x * ROWS;
    const int rowsHere = (int)min((long long)ROWS, (long long)nrows - rowBase);

    const float* srcs[3] = { x1 + rowBase * 32, x2 + rowBase * 32, x3 + rowBase * 32 };

    // ---- mbarrier init (count=1 each) ----
    if (t == 0) {
        #pragma unroll
        for (int in = 0; in < 3; ++in) {
            unsigned mb = (unsigned)__cvta_generic_to_shared(&mbar[in]);
            asm volatile("mbarrier.init.shared.b64 [%0], 1;" :: "r"(mb));
        }
    }
    __syncthreads();

    // ---- issue 3 bulk copies, one completion barrier per input ----
    if (t == 0) {
        const unsigned bytes = (unsigned)(rowsHere * 128);
        #pragma unroll
        for (int in = 0; in < 3; ++in) {
            unsigned mb  = (unsigned)__cvta_generic_to_shared(&mbar[in]);
            unsigned dst = (unsigned)__cvta_generic_to_shared(s + in * IN_FLOATS);
            asm volatile("mbarrier.arrive.expect_tx.shared.b64 _, [%0], %1;"
                         :: "r"(mb), "r"(bytes));
            asm volatile(
                "cp.async.bulk.shared::cta.global.mbarrier::complete_tx::bytes "
                "[%0], [%1], %2, [%3];"
                :: "r"(dst), "l"(srcs[in]), "r"(bytes), "r"(mb) : "memory");
        }
    }
    __syncthreads();   // barrier state visible to all consumers

    // ---- recurrence, consuming each input as its bulk copy lands ----
    float c0 = 1.f, c1 = 0.f, c2 = 0.f, c3 = 0.f, c4 = 0.f, c5 = 0.f;

    #pragma unroll
    for (int in = 0; in < 3; ++in) {
        {   // acquire-wait on this input's barrier, phase parity 0
            unsigned mb = (unsigned)__cvta_generic_to_shared(&mbar[in]);
            unsigned done;
            asm volatile(
                "{\n\t.reg .pred p;\n\t"
                "mbarrier.try_wait.parity.acquire.cta.shared::cta.b64 p, [%1], 0, 0x989680;\n\t"
                "selp.b32 %0, 1, 0, p;\n\t}"
                : "=r"(done) : "r"(mb) : "memory");
            while (!done) {
                asm volatile(
                    "{\n\t.reg .pred p;\n\t"
                    "mbarrier.try_wait.parity.acquire.cta.shared::cta.b64 p, [%1], 0, 0x989680;\n\t"
                    "selp.b32 %0, 1, 0, p;\n\t}"
                    : "=r"(done) : "r"(mb) : "memory");
            }
        }

        // rotation-ordered reads: thread t consumes float4 index (t+i)&7;
        // distinct within each 8-lane phase -> conflict-free without padding.
        // (The distribution is permutation-invariant in the probabilities.)
        const float4* rowp = (const float4*)(s + in * IN_FLOATS + t * 32);
        const int rot = t & 7;
        #pragma unroll
        for (int i = 0; i < 8; ++i) {
            float4 v = rowp[(rot + i) & 7];
            float pv[4] = { v.x, v.y, v.z, v.w };
            #pragma unroll
            for (int u = 0; u < 4; ++u) {
                float p = pv[u];
                c5 = fmaf(c4, p, c5);            // absorbing top bucket (old c4)
                c4 = fmaf(c3 - c4, p, c4);
                c3 = fmaf(c2 - c3, p, c3);
                c2 = fmaf(c1 - c2, p, c2);
                c1 = fmaf(c0 - c1, p, c1);
                c0 = fmaf(-c0, p, c0);           // c0 *= (1-p)
            }
        }
    }
    __syncthreads();   // input tiles fully consumed; reuse smem for output

    // ---- stage output (stride-5 STS, gcd(5,32)=1 -> conflict-free) ----
    float* so = s;     // 320 floats
    so[t * 5 + 0] = c0;
    so[t * 5 + 1] = c1 + c2;
    so[t * 5 + 2] = c3 + c4;
    so[t * 5 + 3] = c5;
    so[t * 5 + 4] = 0.f;
    __syncthreads();

    // ---- drain: vector evict-first stores; scalar fallback on tail ----
    float* og = out + rowBase * 5;
    if (rowsHere == ROWS) {
        float4* og4 = (float4*)og;               // 1280 B/block -> 16B-aligned base
        const float4* so4 = (const float4*)so;
        #pragma unroll
        for (int k = 0; k < 2; ++k) {
            int idx = k * NT + t;                // 0..127, need 80 float4
            if (idx < (ROWS * 5) / 4) __stcs(og4 + idx, so4[idx]);
        }
    } else {
        const int nOut = rowsHere * 5;
        #pragma unroll
        for (int k = 0; k < 5; ++k) {
            int idx = k * NT + t;
            if (idx < nOut) og[idx] = so[idx];
        }
    }
}

extern "C" void kernel_launch(void* const* d_in, const int* in_sizes, int n_in,
                              void* d_out, int out_size)
{
    const float* x1 = (const float*)d_in[0];
    const float* x2 = (const float*)d_in[1];
    const float* x3 = (const float*)d_in[2];
    float* out = (float*)d_out;

    const int nrows = in_sizes[0] / 32;
    const int nblocks = (nrows + ROWS - 1) / ROWS;

    hemorrhage_sev_kernel<<<nblocks, NT>>>(x1, x2, x3, out, nrows);
}

// round 10
// speedup vs baseline: 1.0888x; 1.0039x over previous
#include <cuda_runtime.h>
#include <cuda_bf16.h>
#include <cstdint>

// Clipped Poisson-binomial severity kernel, round 9.
// Same proven one-shot-block machinery as rounds 6/8 (3 cp.async.bulk copies
// per block, per-input mbarriers with progressive waits, rotation-ordered
// conflict-free LDS.128, scalar recurrence, staged .cs float4 stores), taken
// to the finest grain: single-warp blocks (NT=32, ROWS=32, 12.3KB smem ->
// ~18 blocks/SM). All intra-block syncs are warp-level; DRAM demand comes
// from ~54 independent in-flight bulk streams per SM.

#define NT 32                // threads per block (one warp)
#define ROWS 32              // rows per block (1 per thread)
#define IN_FLOATS (ROWS * 32)        // 1024 floats = 4 KB per input tile

__global__ __launch_bounds__(NT)
void hemorrhage_sev_kernel(const float* __restrict__ x1,
                           const float* __restrict__ x2,
                           const float* __restrict__ x3,
                           float* __restrict__ out,
                           int nrows)
{
    __shared__ float s[3 * IN_FLOATS];              // 12,288 B, raw 128B rows
    __shared__ __align__(8) unsigned long long mbar[3];

    const int t = threadIdx.x;
    const long long rowBase = (long long)blockIdx.x * ROWS;
    const int rowsHere = (int)min((long long)ROWS, (long long)nrows - rowBase);

    const float* srcs[3] = { x1 + rowBase * 32, x2 + rowBase * 32, x3 + rowBase * 32 };

    // ---- mbarrier init + issue 3 bulk copies (lane 0) ----
    if (t == 0) {
        const unsigned bytes = (unsigned)(rowsHere * 128);
        #pragma unroll
        for (int in = 0; in < 3; ++in) {
            unsigned mb = (unsigned)__cvta_generic_to_shared(&mbar[in]);
            asm volatile("mbarrier.init.shared.b64 [%0], 1;" :: "r"(mb));
        }
        // make inits visible to the async proxy before TMA targets them
        asm volatile("fence.proxy.async.shared::cta;" ::: "memory");
        #pragma unroll
        for (int in = 0; in < 3; ++in) {
            unsigned mb  = (unsigned)__cvta_generic_to_shared(&mbar[in]);
            unsigned dst = (unsigned)__cvta_generic_to_shared(s + in * IN_FLOATS);
            asm volatile("mbarrier.arrive.expect_tx.shared.b64 _, [%0], %1;"
                         :: "r"(mb), "r"(bytes));
            asm volatile(
                "cp.async.bulk.shared::cta.global.mbarrier::complete_tx::bytes "
                "[%0], [%1], %2, [%3];"
                :: "r"(dst), "l"(srcs[in]), "r"(bytes), "r"(mb) : "memory");
        }
    }
    __syncwarp();    // single-warp block: warp sync is all we need

    // ---- recurrence, consuming each input as its bulk copy lands ----
    float c0 = 1.f, c1 = 0.f, c2 = 0.f, c3 = 0.f, c4 = 0.f, c5 = 0.f;

    #pragma unroll
    for (int in = 0; in < 3; ++in) {
        {   // acquire-wait on this input's barrier, phase parity 0
            unsigned mb = (unsigned)__cvta_generic_to_shared(&mbar[in]);
            unsigned done;
            asm volatile(
                "{\n\t.reg .pred p;\n\t"
                "mbarrier.try_wait.parity.acquire.cta.shared::cta.b64 p, [%1], 0, 0x989680;\n\t"
                "selp.b32 %0, 1, 0, p;\n\t}"
                : "=r"(done) : "r"(mb) : "memory");
            while (!done) {
                asm volatile(
                    "{\n\t.reg .pred p;\n\t"
                    "mbarrier.try_wait.parity.acquire.cta.shared::cta.b64 p, [%1], 0, 0x989680;\n\t"
                    "selp.b32 %0, 1, 0, p;\n\t}"
                    : "=r"(done) : "r"(mb) : "memory");
            }
        }

        // rotation-ordered reads: thread t consumes float4 index (t+i)&7;
        // distinct within each 8-lane phase -> conflict-free without padding.
        // (Distribution is permutation-invariant in the probabilities.)
        const float4* rowp = (const float4*)(s + in * IN_FLOATS + t * 32);
        const int rot = t & 7;
        #pragma unroll
        for (int i = 0; i < 8; ++i) {
            float4 v = rowp[(rot + i) & 7];
            float pv[4] = { v.x, v.y, v.z, v.w };
            #pragma unroll
            for (int u = 0; u < 4; ++u) {
                float p = pv[u];
                c5 = fmaf(c4, p, c5);            // absorbing top bucket (old c4)
                c4 = fmaf(c3 - c4, p, c4);
                c3 = fmaf(c2 - c3, p, c3);
                c2 = fmaf(c1 - c2, p, c2);
                c1 = fmaf(c0 - c1, p, c1);
                c0 = fmaf(-c0, p, c0);           // c0 *= (1-p)
            }
        }
    }
    __syncwarp();    // input tiles fully consumed; reuse smem for output

    // ---- stage output (stride-5 STS, gcd(5,32)=1 -> conflict-free) ----
    float* so = s;   // 160 floats
    so[t * 5 + 0] = c0;
    so[t * 5 + 1] = c1 + c2;
    so[t * 5 + 2] = c3 + c4;
    so[t * 5 + 3] = c5;
    so[t * 5 + 4] = 0.f;
    __syncwarp();

    // ---- drain: vector evict-first stores; scalar fallback on tail ----
    float* og = out + rowBase * 5;
    if (rowsHere == ROWS) {
        float4* og4 = (float4*)og;               // 640 B/block -> 16B-aligned base
        const float4* so4 = (const float4*)so;
        #pragma unroll
        for (int k = 0; k < 2; ++k) {
            int idx = k * NT + t;                // need 40 float4
            if (idx < (ROWS * 5) / 4) __stcs(og4 + idx, so4[idx]);
        }
    } else {
        const int nOut = rowsHere * 5;
        #pragma unroll
        for (int k = 0; k < 5; ++k) {
            int idx = k * NT + t;
            if (idx < nOut) og[idx] = so[idx];
        }
    }
}

extern "C" void kernel_launch(void* const* d_in, const int* in_sizes, int n_in,
                              void* d_out, int out_size)
{
    const float* x1 = (const float*)d_in[0];
    const float* x2 = (const float*)d_in[1];
    const float* x3 = (const float*)d_in[2];
    float* out = (float*)d_out;

    const int nrows = in_sizes[0] / 32;
    const int nblocks = (nrows + ROWS - 1) / ROWS;

    hemorrhage_sev_kernel<<<nblocks, NT>>>(x1, x2, x3, out, nrows);
}

// round 12
// speedup vs baseline: 1.0930x; 1.0039x over previous
#include <cuda_runtime.h>
#include <cuda_bf16.h>
#include <cstdint>

// Clipped Poisson-binomial severity kernel, round 10.
// Identical memory machinery to round 9 (single-warp one-shot blocks, 3
// cp.async.bulk copies with per-input mbarriers + progressive waits,
// rotation-ordered conflict-free LDS.128, staged .cs float4 stores).
// Recurrence now runs in CDF space: S_j = P(count<=j), step
//   S_j -= p*(S_j - S_{j-1}),  S5 == 1 invariant (absorbing bucket is free)
// -> 9 fma-pipe ops/step instead of 10, better ILP, one fewer state reg.
// Outputs: sev = [S0, S2-S0, S4-S2, 1-S4, 0].

#define NT 32                // threads per block (one warp)
#define ROWS 32              // rows per block (1 per thread)
#define IN_FLOATS (ROWS * 32)        // 1024 floats = 4 KB per input tile

__global__ __launch_bounds__(NT)
void hemorrhage_sev_kernel(const float* __restrict__ x1,
                           const float* __restrict__ x2,
                           const float* __restrict__ x3,
                           float* __restrict__ out,
                           int nrows)
{
    __shared__ float s[3 * IN_FLOATS];              // 12,288 B, raw 128B rows
    __shared__ __align__(8) unsigned long long mbar[3];

    const int t = threadIdx.x;
    const long long rowBase = (long long)blockIdx.x * ROWS;
    const int rowsHere = (int)min((long long)ROWS, (long long)nrows - rowBase);

    const float* srcs[3] = { x1 + rowBase * 32, x2 + rowBase * 32, x3 + rowBase * 32 };

    // ---- mbarrier init + issue 3 bulk copies (lane 0) ----
    if (t == 0) {
        const unsigned bytes = (unsigned)(rowsHere * 128);
        #pragma unroll
        for (int in = 0; in < 3; ++in) {
            unsigned mb = (unsigned)__cvta_generic_to_shared(&mbar[in]);
            asm volatile("mbarrier.init.shared.b64 [%0], 1;" :: "r"(mb));
        }
        asm volatile("fence.proxy.async.shared::cta;" ::: "memory");
        #pragma unroll
        for (int in = 0; in < 3; ++in) {
            unsigned mb  = (unsigned)__cvta_generic_to_shared(&mbar[in]);
            unsigned dst = (unsigned)__cvta_generic_to_shared(s + in * IN_FLOATS);
            asm volatile("mbarrier.arrive.expect_tx.shared.b64 _, [%0], %1;"
                         :: "r"(mb), "r"(bytes));
            asm volatile(
                "cp.async.bulk.shared::cta.global.mbarrier::complete_tx::bytes "
                "[%0], [%1], %2, [%3];"
                :: "r"(dst), "l"(srcs[in]), "r"(bytes), "r"(mb) : "memory");
        }
    }
    __syncwarp();

    // ---- CDF recurrence, consuming each input as its bulk copy lands ----
    // S_j = P(count <= j); count starts at 0 -> all ones. S5 == 1 always.
    float S0 = 1.f, S1 = 1.f, S2 = 1.f, S3 = 1.f, S4 = 1.f;

    #pragma unroll
    for (int in = 0; in < 3; ++in) {
        {   // acquire-wait on this input's barrier, phase parity 0
            unsigned mb = (unsigned)__cvta_generic_to_shared(&mbar[in]);
            unsigned done;
            asm volatile(
                "{\n\t.reg .pred p;\n\t"
                "mbarrier.try_wait.parity.acquire.cta.shared::cta.b64 p, [%1], 0, 0x989680;\n\t"
                "selp.b32 %0, 1, 0, p;\n\t}"
                : "=r"(done) : "r"(mb) : "memory");
            while (!done) {
                asm volatile(
                    "{\n\t.reg .pred p;\n\t"
                    "mbarrier.try_wait.parity.acquire.cta.shared::cta.b64 p, [%1], 0, 0x989680;\n\t"
                    "selp.b32 %0, 1, 0, p;\n\t}"
                    : "=r"(done) : "r"(mb) : "memory");
            }
        }

        // rotation-ordered reads: thread t consumes float4 index (t+i)&7;
        // distinct within each 8-lane phase -> conflict-free without padding.
        // (Distribution is permutation-invariant in the probabilities.)
        const float4* rowp = (const float4*)(s + in * IN_FLOATS + t * 32);
        const int rot = t & 7;
        #pragma unroll
        for (int i = 0; i < 8; ++i) {
            float4 v = rowp[(rot + i) & 7];
            float pv[4] = { v.x, v.y, v.z, v.w };
            #pragma unroll
            for (int u = 0; u < 4; ++u) {
                float p = pv[u];
                // 4 independent diffs, then 5 independent FFMAs (good ILP)
                float d4 = S4 - S3;
                float d3 = S3 - S2;
                float d2 = S2 - S1;
                float d1 = S1 - S0;
                S4 = fmaf(-p, d4, S4);
                S3 = fmaf(-p, d3, S3);
                S2 = fmaf(-p, d2, S2);
                S1 = fmaf(-p, d1, S1);
                S0 = fmaf(-p, S0, S0);   // S0 *= (1-p)
            }
        }
    }
    __syncwarp();    // input tiles fully consumed; reuse smem for output

    // ---- stage output (stride-5 STS, gcd(5,32)=1 -> conflict-free) ----
    float* so = s;   // 160 floats
    so[t * 5 + 0] = S0;              // c0
    so[t * 5 + 1] = S2 - S0;         // c1 + c2
    so[t * 5 + 2] = S4 - S2;         // c3 + c4
    so[t * 5 + 3] = 1.f - S4;        // c5
    so[t * 5 + 4] = 0.f;
    __syncwarp();

    // ---- drain: vector evict-first stores; scalar fallback on tail ----
    float* og = out + rowBase * 5;
    if (rowsHere == ROWS) {
        float4* og4 = (float4*)og;               // 640 B/block -> 16B-aligned base
        const float4* so4 = (const float4*)so;
        #pragma unroll
        for (int k = 0; k < 2; ++k) {
            int idx = k * NT + t;                // need 40 float4
            if (idx < (ROWS * 5) / 4) __stcs(og4 + idx, so4[idx]);
        }
    } else {
        const int nOut = rowsHere * 5;
        #pragma unroll
        for (int k = 0; k < 5; ++k) {
            int idx = k * NT + t;
            if (idx < nOut) og[idx] = so[idx];
        }
    }
}

extern "C" void kernel_launch(void* const* d_in, const int* in_sizes, int n_in,
                              void* d_out, int out_size)
{
    const float* x1 = (const float*)d_in[0];
    const float* x2 = (const float*)d_in[1];
    const float* x3 = (const float*)d_in[2];
    float* out = (float*)d_out;

    const int nrows = in_sizes[0] / 32;
    const int nblocks = (nrows + ROWS - 1) / ROWS;

    hemorrhage_sev_kernel<<<nblocks, NT>>>(x1, x2, x3, out, nrows);
}

// round 13
// speedup vs baseline: 1.0946x; 1.0015x over previous
#include <cuda_runtime.h>
#include <cuda_bf16.h>
#include <cstdint>

// Clipped Poisson-binomial severity kernel, round 11.
// Round 10 (best) + L2 evict-first cache-policy hint on the read-once bulk
// copies, so the 384MB input stream self-evicts out of L2 ahead of anything
// else instead of churning the whole cache at normal priority.
// Everything else unchanged: single-warp one-shot blocks, 3 cp.async.bulk
// copies with per-input mbarriers + progressive waits, rotation-ordered
// conflict-free LDS.128, CDF-space recurrence (9 fma-ops/step, S5==1 free),
// staged .cs float4 output stores.

#define NT 32                // threads per block (one warp)
#define ROWS 32              // rows per block (1 per thread)
#define IN_FLOATS (ROWS * 32)        // 1024 floats = 4 KB per input tile

__global__ __launch_bounds__(NT)
void hemorrhage_sev_kernel(const float* __restrict__ x1,
                           const float* __restrict__ x2,
                           const float* __restrict__ x3,
                           float* __restrict__ out,
                           int nrows)
{
    __shared__ float s[3 * IN_FLOATS];              // 12,288 B, raw 128B rows
    __shared__ __align__(8) unsigned long long mbar[3];

    const int t = threadIdx.x;
    const long long rowBase = (long long)blockIdx.x * ROWS;
    const int rowsHere = (int)min((long long)ROWS, (long long)nrows - rowBase);

    const float* srcs[3] = { x1 + rowBase * 32, x2 + rowBase * 32, x3 + rowBase * 32 };

    // ---- mbarrier init + issue 3 bulk copies with evict-first hint (lane 0) ----
    if (t == 0) {
        const unsigned bytes = (unsigned)(rowsHere * 128);
        #pragma unroll
        for (int in = 0; in < 3; ++in) {
            unsigned mb = (unsigned)__cvta_generic_to_shared(&mbar[in]);
            asm volatile("mbarrier.init.shared.b64 [%0], 1;" :: "r"(mb));
        }
        asm volatile("fence.proxy.async.shared::cta;" ::: "memory");

        unsigned long long pol;
        asm volatile("createpolicy.fractional.L2::evict_first.b64 %0, 1.0;"
                     : "=l"(pol));

        #pragma unroll
        for (int in = 0; in < 3; ++in) {
            unsigned mb  = (unsigned)__cvta_generic_to_shared(&mbar[in]);
            unsigned dst = (unsigned)__cvta_generic_to_shared(s + in * IN_FLOATS);
            asm volatile("mbarrier.arrive.expect_tx.shared.b64 _, [%0], %1;"
                         :: "r"(mb), "r"(bytes));
            asm volatile(
                "cp.async.bulk.shared::cta.global.mbarrier::complete_tx::bytes"
                ".L2::cache_hint [%0], [%1], %2, [%3], %4;"
                :: "r"(dst), "l"(srcs[in]), "r"(bytes), "r"(mb), "l"(pol)
                : "memory");
        }
    }
    __syncwarp();

    // ---- CDF recurrence, consuming each input as its bulk copy lands ----
    // S_j = P(count <= j); starts all ones. S5 == 1 invariant (absorbing top).
    float S0 = 1.f, S1 = 1.f, S2 = 1.f, S3 = 1.f, S4 = 1.f;

    #pragma unroll
    for (int in = 0; in < 3; ++in) {
        {   // acquire-wait on this input's barrier, phase parity 0
            unsigned mb = (unsigned)__cvta_generic_to_shared(&mbar[in]);
            unsigned done;
            asm volatile(
                "{\n\t.reg .pred p;\n\t"
                "mbarrier.try_wait.parity.acquire.cta.shared::cta.b64 p, [%1], 0, 0x989680;\n\t"
                "selp.b32 %0, 1, 0, p;\n\t}"
                : "=r"(done) : "r"(mb) : "memory");
            while (!done) {
                asm volatile(
                    "{\n\t.reg .pred p;\n\t"
                    "mbarrier.try_wait.parity.acquire.cta.shared::cta.b64 p, [%1], 0, 0x989680;\n\t"
                    "selp.b32 %0, 1, 0, p;\n\t}"
                    : "=r"(done) : "r"(mb) : "memory");
            }
        }

        // rotation-ordered reads: thread t consumes float4 index (t+i)&7;
        // indices distinct within each 8-lane phase -> conflict-free, no padding.
        // (Distribution is permutation-invariant in the probabilities.)
        const float4* rowp = (const float4*)(s + in * IN_FLOATS + t * 32);
        const int rot = t & 7;
        #pragma unroll
        for (int i = 0; i < 8; ++i) {
            float4 v = rowp[(rot + i) & 7];
            float pv[4] = { v.x, v.y, v.z, v.w };
            #pragma unroll
            for (int u = 0; u < 4; ++u) {
                float p = pv[u];
                float d4 = S4 - S3;
                float d3 = S3 - S2;
                float d2 = S2 - S1;
                float d1 = S1 - S0;
                S4 = fmaf(-p, d4, S4);
                S3 = fmaf(-p, d3, S3);
                S2 = fmaf(-p, d2, S2);
                S1 = fmaf(-p, d1, S1);
                S0 = fmaf(-p, S0, S0);   // S0 *= (1-p)
            }
        }
    }
    __syncwarp();    // input tiles fully consumed; reuse smem for output

    // ---- stage output (stride-5 STS, gcd(5,32)=1 -> conflict-free) ----
    float* so = s;   // 160 floats
    so[t * 5 + 0] = S0;              // c0
    so[t * 5 + 1] = S2 - S0;         // c1 + c2
    so[t * 5 + 2] = S4 - S2;         // c3 + c4
    so[t * 5 + 3] = 1.f - S4;        // c5
    so[t * 5 + 4] = 0.f;
    __syncwarp();

    // ---- drain: vector evict-first stores; scalar fallback on tail ----
    float* og = out + rowBase * 5;
    if (rowsHere == ROWS) {
        float4* og4 = (float4*)og;               // 640 B/block -> 16B-aligned base
        const float4* so4 = (const float4*)so;
        #pragma unroll
        for (int k = 0; k < 2; ++k) {
            int idx = k * NT + t;                // need 40 float4
            if (idx < (ROWS * 5) / 4) __stcs(og4 + idx, so4[idx]);
        }
    } else {
        const int nOut = rowsHere * 5;
        #pragma unroll
        for (int k = 0; k < 5; ++k) {
            int idx = k * NT + t;
            if (idx < nOut) og[idx] = so[idx];
        }
    }
}

extern "C" void kernel_launch(void* const* d_in, const int* in_sizes, int n_in,
                              void* d_out, int out_size)
{
    const float* x1 = (const float*)d_in[0];
    const float* x2 = (const float*)d_in[1];
    const float* x3 = (const float*)d_in[2];
    float* out = (float*)d_out;

    const int nrows = in_sizes[0] / 32;
    const int nblocks = (nrows + ROWS - 1) / ROWS;

    hemorrhage_sev_kernel<<<nblocks, NT>>>(x1, x2, x3, out, nrows);
}

// round 16
// speedup vs baseline: 1.1168x; 1.0203x over previous
#include <cuda_runtime.h>
#include <cuda_bf16.h>
#include <cstdint>

// Clipped Poisson-binomial severity kernel, round 12.
// Round 11 (best) with a 2-slot input ring: x1->slot0, x2->slot1 issued at
// block start; x3->slot0 re-issued (same mbarrier, phase parity 1) right after
// x1 is consumed. smem 12.3KB -> 8.3KB, lifting occupancy 18 -> ~27 blocks/SM
// -- the one axis that has paid consistently all session.
// Unchanged: single-warp one-shot blocks, L2 evict-first policy on bulk reads,
// per-input progressive mbarrier waits, rotation-ordered conflict-free LDS.128,
// CDF-space recurrence (S5==1 invariant), staged .cs float4 output stores.

#define NT 32                // threads per block (one warp)
#define ROWS 32              // rows per block (1 per thread)
#define IN_FLOATS (ROWS * 32)        // 1024 floats = 4 KB per input slot

__device__ __forceinline__ void mbar_wait(unsigned mb, unsigned parity) {
    unsigned done;
    asm volatile(
        "{\n\t.reg .pred p;\n\t"
        "mbarrier.try_wait.parity.acquire.cta.shared::cta.b64 p, [%1], %2, 0x989680;\n\t"
        "selp.b32 %0, 1, 0, p;\n\t}"
        : "=r"(done) : "r"(mb), "r"(parity) : "memory");
    while (!done) {
        asm volatile(
            "{\n\t.reg .pred p;\n\t"
            "mbarrier.try_wait.parity.acquire.cta.shared::cta.b64 p, [%1], %2, 0x989680;\n\t"
            "selp.b32 %0, 1, 0, p;\n\t}"
            : "=r"(done) : "r"(mb), "r"(parity) : "memory");
    }
}

__global__ __launch_bounds__(NT)
void hemorrhage_sev_kernel(const float* __restrict__ x1,
                           const float* __restrict__ x2,
                           const float* __restrict__ x3,
                           float* __restrict__ out,
                           int nrows)
{
    __shared__ float s[2 * IN_FLOATS];              // 8,192 B (2 slots)
    __shared__ __align__(8) unsigned long long mbar[2];

    const int t = threadIdx.x;
    const long long rowBase = (long long)blockIdx.x * ROWS;
    const int rowsHere = (int)min((long long)ROWS, (long long)nrows - rowBase);
    const unsigned bytes = (unsigned)(rowsHere * 128);

    const float* src1 = x1 + rowBase * 32;
    const float* src2 = x2 + rowBase * 32;
    const float* src3 = x3 + rowBase * 32;

    unsigned long long pol = 0;
    const unsigned mb0  = (unsigned)__cvta_generic_to_shared(&mbar[0]);
    const unsigned mb1  = (unsigned)__cvta_generic_to_shared(&mbar[1]);
    const unsigned dst0 = (unsigned)__cvta_generic_to_shared(s);
    const unsigned dst1 = (unsigned)__cvta_generic_to_shared(s + IN_FLOATS);

    // ---- mbarrier init + issue x1 (slot0) and x2 (slot1), evict-first ----
    if (t == 0) {
        asm volatile("mbarrier.init.shared.b64 [%0], 1;" :: "r"(mb0));
        asm volatile("mbarrier.init.shared.b64 [%0], 1;" :: "r"(mb1));
        asm volatile("fence.proxy.async.shared::cta;" ::: "memory");
        asm volatile("createpolicy.fractional.L2::evict_first.b64 %0, 1.0;"
                     : "=l"(pol));
        asm volatile("mbarrier.arrive.expect_tx.shared.b64 _, [%0], %1;"
                     :: "r"(mb0), "r"(bytes));
        asm volatile(
            "cp.async.bulk.shared::cta.global.mbarrier::complete_tx::bytes"
            ".L2::cache_hint [%0], [%1], %2, [%3], %4;"
            :: "r"(dst0), "l"(src1), "r"(bytes), "r"(mb0), "l"(pol) : "memory");
        asm volatile("mbarrier.arrive.expect_tx.shared.b64 _, [%0], %1;"
                     :: "r"(mb1), "r"(bytes));
        asm volatile(
            "cp.async.bulk.shared::cta.global.mbarrier::complete_tx::bytes"
            ".L2::cache_hint [%0], [%1], %2, [%3], %4;"
            :: "r"(dst1), "l"(src2), "r"(bytes), "r"(mb1), "l"(pol) : "memory");
    }
    __syncwarp();

    // ---- CDF recurrence: S_j = P(count<=j), S5 == 1 invariant ----
    float S0 = 1.f, S1 = 1.f, S2 = 1.f, S3 = 1.f, S4 = 1.f;
    const int rot = t & 7;

    auto consume = [&](const float* slot) {
        const float4* rowp = (const float4*)(slot + t * 32);
        #pragma unroll
        for (int i = 0; i < 8; ++i) {
            float4 v = rowp[(rot + i) & 7];   // conflict-free rotation order
            float pv[4] = { v.x, v.y, v.z, v.w };
            #pragma unroll
            for (int u = 0; u < 4; ++u) {
                float p = pv[u];
                float d4 = S4 - S3;
                float d3 = S3 - S2;
                float d2 = S2 - S1;
                float d1 = S1 - S0;
                S4 = fmaf(-p, d4, S4);
                S3 = fmaf(-p, d3, S3);
                S2 = fmaf(-p, d2, S2);
                S1 = fmaf(-p, d1, S1);
                S0 = fmaf(-p, S0, S0);        // S0 *= (1-p)
            }
        }
    };

    // x1: slot0, phase 0
    mbar_wait(mb0, 0);
    consume(s);

    // slot0 free -> re-issue for x3 (completion = phase parity 1)
    __syncwarp();                                  // all lanes done reading slot0
    if (t == 0) {
        asm volatile("fence.proxy.async.shared::cta;" ::: "memory");
        asm volatile("mbarrier.arrive.expect_tx.shared.b64 _, [%0], %1;"
                     :: "r"(mb0), "r"(bytes));
        asm volatile(
            "cp.async.bulk.shared::cta.global.mbarrier::complete_tx::bytes"
            ".L2::cache_hint [%0], [%1], %2, [%3], %4;"
            :: "r"(dst0), "l"(src3), "r"(bytes), "r"(mb0), "l"(pol) : "memory");
    }

    // x2: slot1, phase 0
    mbar_wait(mb1, 0);
    consume(s + IN_FLOATS);

    // x3: slot0, phase 1
    mbar_wait(mb0, 1);
    consume(s);

    __syncwarp();   // inputs fully consumed; reuse slot0 for output staging

    // ---- stage output (stride-5 STS, gcd(5,32)=1 -> conflict-free) ----
    float* so = s;  // 160 floats
    so[t * 5 + 0] = S0;              // c0
    so[t * 5 + 1] = S2 - S0;         // c1 + c2
    so[t * 5 + 2] = S4 - S2;         // c3 + c4
    so[t * 5 + 3] = 1.f - S4;        // c5
    so[t * 5 + 4] = 0.f;
    __syncwarp();

    // ---- drain: vector evict-first stores; scalar fallback on tail ----
    float* og = out + rowBase * 5;
    if (rowsHere == ROWS) {
        float4* og4 = (float4*)og;               // 640 B/block -> 16B-aligned base
        const float4* so4 = (const float4*)so;
        #pragma unroll
        for (int k = 0; k < 2; ++k) {
            int idx = k * NT + t;                // need 40 float4
            if (idx < (ROWS * 5) / 4) __stcs(og4 + idx, so4[idx]);
        }
    } else {
        const int nOut = rowsHere * 5;
        #pragma unroll
        for (int k = 0; k < 5; ++k) {
            int idx = k * NT + t;
            if (idx < nOut) og[idx] = so[idx];
        }
    }
}

extern "C" void kernel_launch(void* const* d_in, const int* in_sizes, int n_in,
                              void* d_out, int out_size)
{
    const float* x1 = (const float*)d_in[0];
    const float* x2 = (const float*)d_in[1];
    const float* x3 = (const float*)d_in[2];
    float* out = (float*)d_out;

    const int nrows = in_sizes[0] / 32;
    const int nblocks = (nrows + ROWS - 1) / ROWS;

    hemorrhage_sev_kernel<<<nblocks, NT>>>(x1, x2, x3, out, nrows);
}

// round 17
// speedup vs baseline: 1.2389x; 1.1093x over previous
#include <cuda_runtime.h>
#include <cuda_bf16.h>
#include <cstdint>

// Clipped Poisson-binomial severity kernel, round 13.
// Round 12 (best) + cp.async.bulk.prefetch.L2 of the x3 range at block start:
// the 2-slot ring defers x3's smem fill until x1 is consumed, but the L2
// prefetch restores full 3-stream DRAM demand up front (no smem needed), so
// the deferred bulk copy becomes an L2 hit instead of a cold DRAM fetch.
// Unchanged: single-warp one-shot blocks, 2-slot ring, L2 evict-first policy,
// per-input progressive mbarrier waits, rotation-ordered conflict-free
// LDS.128, CDF-space recurrence (S5==1 invariant), staged .cs float4 stores.

#define NT 32                // threads per block (one warp)
#define ROWS 32              // rows per block (1 per thread)
#define IN_FLOATS (ROWS * 32)        // 1024 floats = 4 KB per input slot

__device__ __forceinline__ void mbar_wait(unsigned mb, unsigned parity) {
    unsigned done;
    asm volatile(
        "{\n\t.reg .pred p;\n\t"
        "mbarrier.try_wait.parity.acquire.cta.shared::cta.b64 p, [%1], %2, 0x989680;\n\t"
        "selp.b32 %0, 1, 0, p;\n\t}"
        : "=r"(done) : "r"(mb), "r"(parity) : "memory");
    while (!done) {
        asm volatile(
            "{\n\t.reg .pred p;\n\t"
            "mbarrier.try_wait.parity.acquire.cta.shared::cta.b64 p, [%1], %2, 0x989680;\n\t"
            "selp.b32 %0, 1, 0, p;\n\t}"
            : "=r"(done) : "r"(mb), "r"(parity) : "memory");
    }
}

__global__ __launch_bounds__(NT)
void hemorrhage_sev_kernel(const float* __restrict__ x1,
                           const float* __restrict__ x2,
                           const float* __restrict__ x3,
                           float* __restrict__ out,
                           int nrows)
{
    __shared__ float s[2 * IN_FLOATS];              // 8,192 B (2 slots)
    __shared__ __align__(8) unsigned long long mbar[2];

    const int t = threadIdx.x;
    const long long rowBase = (long long)blockIdx.x * ROWS;
    const int rowsHere = (int)min((long long)ROWS, (long long)nrows - rowBase);
    const unsigned bytes = (unsigned)(rowsHere * 128);

    const float* src1 = x1 + rowBase * 32;
    const float* src2 = x2 + rowBase * 32;
    const float* src3 = x3 + rowBase * 32;

    unsigned long long pol = 0;
    const unsigned mb0  = (unsigned)__cvta_generic_to_shared(&mbar[0]);
    const unsigned mb1  = (unsigned)__cvta_generic_to_shared(&mbar[1]);
    const unsigned dst0 = (unsigned)__cvta_generic_to_shared(s);
    const unsigned dst1 = (unsigned)__cvta_generic_to_shared(s + IN_FLOATS);

    // ---- init + issue x1 (slot0), x2 (slot1), and L2-prefetch x3 ----
    if (t == 0) {
        asm volatile("mbarrier.init.shared.b64 [%0], 1;" :: "r"(mb0));
        asm volatile("mbarrier.init.shared.b64 [%0], 1;" :: "r"(mb1));
        asm volatile("fence.proxy.async.shared::cta;" ::: "memory");
        asm volatile("createpolicy.fractional.L2::evict_first.b64 %0, 1.0;"
                     : "=l"(pol));
        asm volatile("mbarrier.arrive.expect_tx.shared.b64 _, [%0], %1;"
                     :: "r"(mb0), "r"(bytes));
        asm volatile(
            "cp.async.bulk.shared::cta.global.mbarrier::complete_tx::bytes"
            ".L2::cache_hint [%0], [%1], %2, [%3], %4;"
            :: "r"(dst0), "l"(src1), "r"(bytes), "r"(mb0), "l"(pol) : "memory");
        asm volatile("mbarrier.arrive.expect_tx.shared.b64 _, [%0], %1;"
                     :: "r"(mb1), "r"(bytes));
        asm volatile(
            "cp.async.bulk.shared::cta.global.mbarrier::complete_tx::bytes"
            ".L2::cache_hint [%0], [%1], %2, [%3], %4;"
            :: "r"(dst1), "l"(src2), "r"(bytes), "r"(mb1), "l"(pol) : "memory");
        // front-load x3's DRAM demand into L2 (no smem slot required)
        asm volatile(
            "cp.async.bulk.prefetch.L2.global.L2::cache_hint [%0], %1, %2;"
            :: "l"(src3), "r"(bytes), "l"(pol) : "memory");
    }
    __syncwarp();

    // ---- CDF recurrence: S_j = P(count<=j), S5 == 1 invariant ----
    float S0 = 1.f, S1 = 1.f, S2 = 1.f, S3 = 1.f, S4 = 1.f;
    const int rot = t & 7;

    auto consume = [&](const float* slot) {
        const float4* rowp = (const float4*)(slot + t * 32);
        #pragma unroll
        for (int i = 0; i < 8; ++i) {
            float4 v = rowp[(rot + i) & 7];   // conflict-free rotation order
            float pv[4] = { v.x, v.y, v.z, v.w };
            #pragma unroll
            for (int u = 0; u < 4; ++u) {
                float p = pv[u];
                float d4 = S4 - S3;
                float d3 = S3 - S2;
                float d2 = S2 - S1;
                float d1 = S1 - S0;
                S4 = fmaf(-p, d4, S4);
                S3 = fmaf(-p, d3, S3);
                S2 = fmaf(-p, d2, S2);
                S1 = fmaf(-p, d1, S1);
                S0 = fmaf(-p, S0, S0);        // S0 *= (1-p)
            }
        }
    };

    // x1: slot0, phase 0
    mbar_wait(mb0, 0);
    consume(s);

    // slot0 free -> re-issue for x3 (completion = phase parity 1); L2 hit now
    __syncwarp();                                  // all lanes done reading slot0
    if (t == 0) {
        asm volatile("fence.proxy.async.shared::cta;" ::: "memory");
        asm volatile("mbarrier.arrive.expect_tx.shared.b64 _, [%0], %1;"
                     :: "r"(mb0), "r"(bytes));
        asm volatile(
            "cp.async.bulk.shared::cta.global.mbarrier::complete_tx::bytes"
            ".L2::cache_hint [%0], [%1], %2, [%3], %4;"
            :: "r"(dst0), "l"(src3), "r"(bytes), "r"(mb0), "l"(pol) : "memory");
    }

    // x2: slot1, phase 0
    mbar_wait(mb1, 0);
    consume(s + IN_FLOATS);

    // x3: slot0, phase 1
    mbar_wait(mb0, 1);
    consume(s);

    __syncwarp();   // inputs fully consumed; reuse slot0 for output staging

    // ---- stage output (stride-5 STS, gcd(5,32)=1 -> conflict-free) ----
    float* so = s;  // 160 floats
    so[t * 5 + 0] = S0;              // c0
    so[t * 5 + 1] = S2 - S0;         // c1 + c2
    so[t * 5 + 2] = S4 - S2;         // c3 + c4
    so[t * 5 + 3] = 1.f - S4;        // c5
    so[t * 5 + 4] = 0.f;
    __syncwarp();

    // ---- drain: vector evict-first stores; scalar fallback on tail ----
    float* og = out + rowBase * 5;
    if (rowsHere == ROWS) {
        float4* og4 = (float4*)og;               // 640 B/block -> 16B-aligned base
        const float4* so4 = (const float4*)so;
        #pragma unroll
        for (int k = 0; k < 2; ++k) {
            int idx = k * NT + t;                // need 40 float4
            if (idx < (ROWS * 5) / 4) __stcs(og4 + idx, so4[idx]);
        }
    } else {
        const int nOut = rowsHere * 5;
        #pragma unroll
        for (int k = 0; k < 5; ++k) {
            int idx = k * NT + t;
            if (idx < nOut) og[idx] = so[idx];
        }
    }
}

extern "C" void kernel_launch(void* const* d_in, const int* in_sizes, int n_in,
                              void* d_out, int out_size)
{
    const float* x1 = (const float*)d_in[0];
    const float* x2 = (const float*)d_in[1];
    const float* x3 = (const float*)d_in[2];
    float* out = (float*)d_out;

    const int nrows = in_sizes[0] / 32;
    const int nblocks = (nrows + ROWS - 1) / ROWS;

    hemorrhage_sev_kernel<<<nblocks, NT>>>(x1, x2, x3, out, nrows);
}